// round 1
// baseline (speedup 1.0000x reference)
#include <cuda_runtime.h>
#include <math.h>

#define KDIM 1024
#define NDIM 16384
#define NCHUNK 128
#define CHUNKL 128

// Scratch (device globals: allocation-free rule)
__device__ float  g_Gt[(size_t)KDIM * NDIM];   // Gt[k][t] = Beta[k] * S_t[k]
__device__ float  g_Mu0[KDIM];
__device__ double g_partials[1024];

// ---------------------------------------------------------------------------
// Kernel 1: Mu0[k] = mean(obs[k,:]) / 10 + 1e-5
// ---------------------------------------------------------------------------
__global__ void mu0_kernel(const float* __restrict__ obs) {
    int k = blockIdx.x;
    const float* row = obs + (size_t)k * NDIM;
    float s = 0.0f;
    for (int t = threadIdx.x; t < NDIM; t += blockDim.x) s += row[t];
    __shared__ float sred[256];
    sred[threadIdx.x] = s;
    __syncthreads();
    for (int off = 128; off > 0; off >>= 1) {
        if (threadIdx.x < off) sred[threadIdx.x] += sred[threadIdx.x + off];
        __syncthreads();
    }
    if (threadIdx.x == 0)
        g_Mu0[k] = sred[0] / (float)(NDIM * 10) + 1e-5f;
}

// ---------------------------------------------------------------------------
// Kernel 2: chunked linear scan per row.
//   S_0 = 0 ; emit G[t] = Beta*S_t ; S_{t+1} = d*(S_t + obs[t]),  d = exp(-Beta)
// Chunk of length L: C accumulates same recurrence from 0; carry multiplier
// d^L = exp(-128*Beta) underflows to ~0 for Beta>=1 — mathematically negligible.
// One block per k, one thread per chunk.
// ---------------------------------------------------------------------------
__global__ void scan_kernel(const float* __restrict__ obs,
                            const float* __restrict__ Beta) {
    int k = blockIdx.x;
    int c = threadIdx.x;                 // chunk id, 0..127
    float betak = Beta[k];
    float d = expf(-betak);
    const float* row = obs + (size_t)k * NDIM;
    int base = c * CHUNKL;

    // Phase A: chunk-local additive term C (recurrence with S=0 start)
    float C = 0.0f;
#pragma unroll 4
    for (int i = 0; i < CHUNKL; i++) C = d * (C + row[base + i]);

    __shared__ float sC[NCHUNK];
    __shared__ float sS[NCHUNK];
    sC[c] = C;
    __syncthreads();

    // Phase B: exclusive scan over chunks (serial, 128 steps, thread 0)
    if (c == 0) {
        // d^128 via repeated squaring
        float dl = d;
#pragma unroll
        for (int q = 0; q < 7; q++) dl *= dl;
        float S = 0.0f;
        for (int c2 = 0; c2 < NCHUNK; c2++) {
            sS[c2] = S;
            S = dl * S + sC[c2];
        }
    }
    __syncthreads();

    // Phase C: replay chunk, emitting Gt[k][t] = Beta * S_t
    float S = sS[c];
    float* gt = g_Gt + (size_t)k * NDIM + base;
#pragma unroll 4
    for (int i = 0; i < CHUNKL; i++) {
        gt[i] = betak * S;
        S = d * (S + row[base + i]);
    }
}

// ---------------------------------------------------------------------------
// Kernel 3: fused GEMM + epilogue
//   lam1[k,t] = softplus( sum_j Alpha[k,j] * Gt[j,t] ),  lam1[:,0] = 0
//   writes lams0, lam1, and per-block double partial of the log-likelihood.
// C is [K=1024 (k rows) x N=16384 (t cols)], tiles 128x128x16, 256 thr, 8x8/thr
// ---------------------------------------------------------------------------
#define BM 128
#define BN 128
#define BK 16

__device__ __forceinline__ float softplus_f(float x) {
    return (x > 20.0f) ? x : log1pf(expf(x));
}

__global__ __launch_bounds__(256, 1)
void gemm_epi_kernel(const float* __restrict__ Alpha,
                     const float* __restrict__ obs,
                     float* __restrict__ out, long long out_size) {
    __shared__ float As[BK][BM];   // As[j][k-row]
    __shared__ float Bs[BK][BN];   // Bs[j][t-col]

    int tid = threadIdx.x;
    int tx = tid & 15;             // t sub-tile
    int ty = tid >> 4;             // k sub-tile
    int t0 = blockIdx.x * BN;
    int k0 = blockIdx.y * BM;

    float acc[8][8];
#pragma unroll
    for (int i = 0; i < 8; i++)
#pragma unroll
        for (int j = 0; j < 8; j++) acc[i][j] = 0.0f;

    for (int kt = 0; kt < KDIM / BK; kt++) {
        int j0 = kt * BK;
        // load A tile: Alpha[k0+r][j0+c], 128x16 floats = 512 float4
#pragma unroll
        for (int pp = 0; pp < 2; pp++) {
            int p = tid + pp * 256;
            int r = p >> 2;
            int c4 = p & 3;
            float4 v = *(const float4*)(Alpha + (size_t)(k0 + r) * KDIM + j0 + c4 * 4);
            As[c4 * 4 + 0][r] = v.x;
            As[c4 * 4 + 1][r] = v.y;
            As[c4 * 4 + 2][r] = v.z;
            As[c4 * 4 + 3][r] = v.w;
        }
        // load B tile: Gt[j0+r][t0+c], 16x128 floats = 512 float4
#pragma unroll
        for (int pp = 0; pp < 2; pp++) {
            int p = tid + pp * 256;
            int r = p >> 5;
            int c4 = p & 31;
            float4 v = *(const float4*)(g_Gt + (size_t)(j0 + r) * NDIM + t0 + c4 * 4);
            *(float4*)(&Bs[r][c4 * 4]) = v;
        }
        __syncthreads();

#pragma unroll
        for (int kk = 0; kk < BK; kk++) {
            float a[8], b[8];
            *(float4*)(&a[0]) = *(const float4*)(&As[kk][ty * 8]);
            *(float4*)(&a[4]) = *(const float4*)(&As[kk][ty * 8 + 4]);
            *(float4*)(&b[0]) = *(const float4*)(&Bs[kk][tx * 8]);
            *(float4*)(&b[4]) = *(const float4*)(&Bs[kk][tx * 8 + 4]);
#pragma unroll
            for (int i = 0; i < 8; i++)
#pragma unroll
                for (int j = 0; j < 8; j++) acc[i][j] = fmaf(a[i], b[j], acc[i][j]);
        }
        __syncthreads();
    }

    // Epilogue
    const long long KN = (long long)KDIM * NDIM;
    bool full_out = (out_size >= 1 + 2 * KN);
    float* out_lams0 = out + 1;
    float* out_lam1  = out + 1 + KN;

    double lsum = 0.0;
#pragma unroll
    for (int i = 0; i < 8; i++) {
        int k = k0 + ty * 8 + i;
        float mu = g_Mu0[k];
#pragma unroll
        for (int j = 0; j < 8; j++) {
            int t = t0 + tx * 8 + j;
            float lam = softplus_f(acc[i][j]);
            if (t == 0) lam = 0.0f;
            size_t idx = (size_t)k * NDIM + t;
            if (full_out) {
                out_lams0[idx] = mu;
                out_lam1[idx]  = lam;
            }
            float o = obs[idx];
            lsum += (double)(o * logf(mu + lam + 1e-5f) - mu - lam);
        }
    }

    // block-reduce double partial
    __shared__ double dred[256];
    dred[tid] = lsum;
    __syncthreads();
    for (int off = 128; off > 0; off >>= 1) {
        if (tid < off) dred[tid] += dred[tid + off];
        __syncthreads();
    }
    if (tid == 0)
        g_partials[blockIdx.y * gridDim.x + blockIdx.x] = dred[0];
}

// ---------------------------------------------------------------------------
// Kernel 4: deterministic final reduction of 1024 double partials -> out[0]
// ---------------------------------------------------------------------------
__global__ void final_reduce_kernel(float* __restrict__ out) {
    __shared__ double dred[256];
    int tid = threadIdx.x;
    double s = 0.0;
    for (int i = tid; i < 1024; i += 256) s += g_partials[i];
    dred[tid] = s;
    __syncthreads();
    for (int off = 128; off > 0; off >>= 1) {
        if (tid < off) dred[tid] += dred[tid + off];
        __syncthreads();
    }
    if (tid == 0) out[0] = (float)dred[0];
}

// ---------------------------------------------------------------------------
extern "C" void kernel_launch(void* const* d_in, const int* in_sizes, int n_in,
                              void* d_out, int out_size) {
    const float* obs   = (const float*)d_in[0];   // [K, N]
    const float* Beta  = (const float*)d_in[1];   // [K]
    const float* Alpha = (const float*)d_in[2];   // [K, K]
    float* out = (float*)d_out;

    mu0_kernel<<<KDIM, 256>>>(obs);
    scan_kernel<<<KDIM, NCHUNK>>>(obs, Beta);

    dim3 grid(NDIM / BN, KDIM / BM);  // (128, 8)
    gemm_epi_kernel<<<grid, 256>>>(Alpha, obs, out, (long long)out_size);

    final_reduce_kernel<<<1, 256>>>(out);
}

// round 5
// speedup vs baseline: 3.0549x; 3.0549x over previous
#include <cuda_runtime.h>
#include <cuda_bf16.h>
#include <math.h>
#include <stdint.h>

#define KDIM 1024
#define NDIM 16384
#define NCHUNK 128
#define CHUNKL 128

// Feature gate: tcgen05 only exists on the sm_103a ('a'-feature) compile pass.
#if defined(__CUDA_ARCH_FEAT_SM103_ALL)
#define TC_PATH 1
#else
#define TC_PATH 0
#endif

// ---------------------------------------------------------------------------
// Scratch (device globals: allocation-free rule)
// ---------------------------------------------------------------------------
__device__ __nv_bfloat16 g_Abf[(size_t)KDIM * KDIM];   // Alpha bf16 [k][j]
__device__ __nv_bfloat16 g_Gbf[(size_t)NDIM * KDIM];   // G bf16 [t][j]  (B operand, K-major)
__device__ float  g_Scar[(size_t)KDIM * NCHUNK];       // chunk-start S values
__device__ float  g_Mu0[KDIM];
__device__ double g_partials[1024];

// ---------------------------------------------------------------------------
// PTX helpers (sm_103a)
// ---------------------------------------------------------------------------
__device__ __forceinline__ uint32_t smem_u32(const void* p) {
    uint32_t a;
    asm("{ .reg .u64 t; cvta.to.shared.u64 t, %1; cvt.u32.u64 %0, t; }" : "=r"(a) : "l"(p));
    return a;
}
__device__ __forceinline__ uint32_t elect_one() {
    uint32_t p;
    asm volatile("{\n\t.reg .pred p;\n\telect.sync _|p, 0xFFFFFFFF;\n\tselp.b32 %0, 1, 0, p;\n\t}" : "=r"(p));
    return p;
}
#define SMEM_SWIZZLE_128B(x) ((x) ^ (((x) >> 3) & 0x70))

static __device__ constexpr uint64_t SMEM_DESC_BASE_SW128 =
    (uint64_t(2) << 61) | (uint64_t(1) << 46) | (uint64_t(64) << 32) | (uint64_t(1) << 16);
#define MAKE_SMEM_DESC(a) (SMEM_DESC_BASE_SW128 | ((uint64_t)((a) >> 4) & 0x3FFF))

#define TCGEN05_ALLOC(sm, n) \
    asm volatile("tcgen05.alloc.cta_group::1.sync.aligned.shared::cta.b32 [%0], %1;" :: "r"((uint32_t)(sm)), "r"((uint32_t)(n)) : "memory")
#define TCGEN05_DEALLOC(tm, n) \
    asm volatile("tcgen05.dealloc.cta_group::1.sync.aligned.b32 %0, %1;" :: "r"(tm), "r"((uint32_t)(n)))
#define TCGEN05_RELINQ() \
    asm volatile("tcgen05.relinquish_alloc_permit.cta_group::1.sync.aligned;")
#define TCGEN05_COMMIT(mb) \
    asm volatile("tcgen05.commit.cta_group::1.mbarrier::arrive::one.shared::cluster.b64 [%0];" :: "r"((uint32_t)(mb)) : "memory")
#define TCGEN05_WAIT_LD()  asm volatile("tcgen05.wait::ld.sync.aligned;" ::: "memory")
#define TCGEN05_FENCE_AFTER() asm volatile("tcgen05.fence::after_thread_sync;" ::: "memory")
#define TCGEN05_FENCE_BEFORE() asm volatile("tcgen05.fence::before_thread_sync;" ::: "memory")
#define FENCE_PROXY_ASYNC() asm volatile("fence.proxy.async.shared::cta;" ::: "memory")
#define MBARRIER_INIT(mb, c) \
    asm volatile("mbarrier.init.shared.b64 [%0], %1;" :: "r"((uint32_t)(mb)), "r"((uint32_t)(c)) : "memory")
#define MBARRIER_INVAL(mb) \
    asm volatile("mbarrier.inval.shared.b64 [%0];" :: "r"((uint32_t)(mb)) : "memory")

__device__ __forceinline__ void mbar_wait(uint32_t addr, uint32_t parity) {
    asm volatile(
        "{\n\t.reg .pred P;\n\t"
        "LW%=:\n\t"
        "mbarrier.try_wait.parity.acquire.cta.shared::cta.b64 P, [%0], %1, 0x989680;\n\t"
        "@!P bra LW%=;\n\t}"
        :: "r"(addr), "r"(parity) : "memory");
}

#if TC_PATH
#define TCGEN05_LD_X32(r, tm) \
    asm volatile( \
        "tcgen05.ld.sync.aligned.32x32b.x32.b32 " \
        "{%0, %1, %2, %3, %4, %5, %6, %7, " \
        " %8, %9, %10, %11, %12, %13, %14, %15, " \
        " %16, %17, %18, %19, %20, %21, %22, %23, " \
        " %24, %25, %26, %27, %28, %29, %30, %31}, [%32];" \
        : "=r"((r)[0]),  "=r"((r)[1]),  "=r"((r)[2]),  "=r"((r)[3]), \
          "=r"((r)[4]),  "=r"((r)[5]),  "=r"((r)[6]),  "=r"((r)[7]), \
          "=r"((r)[8]),  "=r"((r)[9]),  "=r"((r)[10]), "=r"((r)[11]), \
          "=r"((r)[12]), "=r"((r)[13]), "=r"((r)[14]), "=r"((r)[15]), \
          "=r"((r)[16]), "=r"((r)[17]), "=r"((r)[18]), "=r"((r)[19]), \
          "=r"((r)[20]), "=r"((r)[21]), "=r"((r)[22]), "=r"((r)[23]), \
          "=r"((r)[24]), "=r"((r)[25]), "=r"((r)[26]), "=r"((r)[27]), \
          "=r"((r)[28]), "=r"((r)[29]), "=r"((r)[30]), "=r"((r)[31]) \
        : "r"(tm))

__device__ __forceinline__ void mma_f16_ss(uint32_t d_tmem, uint64_t a_desc,
                                           uint64_t b_desc, uint32_t idesc, bool en) {
    uint32_t e = en ? 1u : 0u;
    asm volatile(
        "{\n\t.reg .pred p;\n\t"
        "setp.ne.u32 p, %5, 0;\n\t"
        "tcgen05.mma.cta_group::1.kind::f16 [%0], %1, %2, %3, {%4, %4, %4, %4}, p;\n\t}"
        :: "r"(d_tmem), "l"(a_desc), "l"(b_desc), "r"(idesc), "r"(0u), "r"(e)
        : "memory");
}
#endif  // TC_PATH

// idesc: F32 accum, bf16 A/B, M=128, N=128
#define GEMM_IDESC 0x8200490u

// ---------------------------------------------------------------------------
// Kernel 1: carry pass. One block per k. Computes chunk-start S values and Mu0.
// ---------------------------------------------------------------------------
__global__ void carry_kernel(const float* __restrict__ obs,
                             const float* __restrict__ Beta) {
    int k = blockIdx.x;
    int c = threadIdx.x;                  // chunk id
    float betak = Beta[k];
    float d = expf(-betak);
    const float* row = obs + (size_t)k * NDIM + c * CHUNKL;

    float C = 0.0f, sum = 0.0f;
#pragma unroll 4
    for (int i = 0; i < CHUNKL; i++) {
        float o = row[i];
        C = d * (C + o);
        sum += o;
    }

    __shared__ float sC[NCHUNK];
    __shared__ float sS[NCHUNK];
    __shared__ float ssum[NCHUNK];
    sC[c] = C;
    ssum[c] = sum;
    __syncthreads();

    if (c == 0) {
        float dl = d;
#pragma unroll
        for (int q = 0; q < 7; q++) dl *= dl;   // d^128 (≈0, kept for exactness)
        float S = 0.0f;
        for (int c2 = 0; c2 < NCHUNK; c2++) {
            sS[c2] = S;
            S = dl * S + sC[c2];
        }
    }
    // reduce row sum for Mu0
    for (int off = 64; off > 0; off >>= 1) {
        __syncthreads();
        if (c < off) ssum[c] += ssum[c + off];
    }
    __syncthreads();
    g_Scar[(size_t)k * NCHUNK + c] = sS[c];
    if (c == 0)
        g_Mu0[k] = ssum[0] / (float)(NDIM * 10) + 1e-5f;
}

// ---------------------------------------------------------------------------
// Kernel 2: emit pass. Grid (128 t-chunks, 8 k-groups), 128 threads = 128 k.
// Replays the recurrence and writes G transposed as bf16: g_Gbf[t][k].
// ---------------------------------------------------------------------------
__global__ void emit_kernel(const float* __restrict__ obs,
                            const float* __restrict__ Beta) {
    int c = blockIdx.x;                   // t chunk
    int k = blockIdx.y * 128 + threadIdx.x;
    float betak = Beta[k];
    float d = expf(-betak);
    float S = g_Scar[(size_t)k * NCHUNK + c];
    const float* row = obs + (size_t)k * NDIM + c * CHUNKL;
    __nv_bfloat16* gout = g_Gbf + (size_t)c * CHUNKL * KDIM + k;
#pragma unroll 4
    for (int i = 0; i < CHUNKL; i++) {
        gout[(size_t)i * KDIM] = __float2bfloat16_rn(betak * S);
        S = d * (S + row[i]);
    }
}

// ---------------------------------------------------------------------------
// Kernel 3: Alpha -> bf16
// ---------------------------------------------------------------------------
__global__ void convA_kernel(const float* __restrict__ Alpha) {
    size_t i4 = (size_t)blockIdx.x * blockDim.x + threadIdx.x;  // float4 index
    float4 v = ((const float4*)Alpha)[i4];
    __nv_bfloat162 lo, hi;
    lo.x = __float2bfloat16_rn(v.x); lo.y = __float2bfloat16_rn(v.y);
    hi.x = __float2bfloat16_rn(v.z); hi.y = __float2bfloat16_rn(v.w);
    ((__nv_bfloat162*)g_Abf)[i4 * 2]     = lo;
    ((__nv_bfloat162*)g_Abf)[i4 * 2 + 1] = hi;
}

// ---------------------------------------------------------------------------
// Kernel 4: tcgen05 GEMM + fused epilogue.
// Tile 128(M=k) x 128(N=t), K chunk = 64 bf16 (one SW128 atom), 16 chunks,
// double-buffered SMEM, per-chunk commit into alternating mbarriers.
// ---------------------------------------------------------------------------
#define GM 128
#define GN 128
#define GK 64
#define NCH (KDIM / GK)       // 16

#define OFF_TPTR  0
#define OFF_MBAR  16          // two 8-byte mbarriers at 16, 24
#define OFF_A(b)  (1024 + (b) * 32768)
#define OFF_B(b)  (1024 + (b) * 32768 + 16384)
#define GEMM_SMEM (1024 + 2 * 32768)

__device__ __forceinline__ void load_tile(char* smem, int off,
                                          const __nv_bfloat16* src) {
    int tid = threadIdx.x;
#pragma unroll
    for (int p = 0; p < 4; p++) {
        int q = tid + p * 256;            // 0..1023
        int r = q >> 3;                   // row 0..127
        int cc = q & 7;                   // 16B chunk in row
        uint32_t bo = r * 128 + cc * 16;
        uint32_t sw = SMEM_SWIZZLE_128B(bo);
        *(uint4*)(smem + off + sw) = *(const uint4*)(src + (size_t)r * KDIM + cc * 8);
    }
}

__device__ __forceinline__ float softplus_f(float x) {
    return (x > 20.0f) ? x : log1pf(expf(x));
}

__global__ __launch_bounds__(256, 2)
void gemm_kernel(const float* __restrict__ obs,
                 float* __restrict__ out, long long out_size) {
    extern __shared__ char smem[];
    int tid = threadIdx.x;
    int t0 = blockIdx.x * GN;
    int k0 = blockIdx.y * GM;
    const long long KN = (long long)KDIM * NDIM;
    bool full_out = (out_size >= 1 + 2 * KN);
    // NOTE: these bases are offset 4B from the 256B-aligned allocation —
    // only 32-bit stores are legal through them.
    float* out_lams0 = out + 1;
    float* out_lam1  = out + 1 + KN;

#if TC_PATH
    uint32_t smem_base = smem_u32(smem);
    int wid = tid >> 5;
    int lid = tid & 31;

    if (tid == 0) {
        MBARRIER_INIT(smem_base + OFF_MBAR, 1);
        MBARRIER_INIT(smem_base + OFF_MBAR + 8, 1);
    }
    if (wid == 0) {
        TCGEN05_ALLOC(smem_base + OFF_TPTR, 128);
        TCGEN05_RELINQ();
    }
    __syncthreads();
    uint32_t tmem_base;
    asm volatile("ld.shared.b32 %0, [%1];" : "=r"(tmem_base) : "r"(smem_base + OFF_TPTR));

    // preload chunk 0 into buffer 0
    load_tile(smem, OFF_A(0), g_Abf + (size_t)k0 * KDIM);
    load_tile(smem, OFF_B(0), g_Gbf + (size_t)t0 * KDIM);
    FENCE_PROXY_ASYNC();
    __syncthreads();

    int ph0 = 0, ph1 = 0;
    for (int c = 0; c < NCH; c++) {
        int b = c & 1;
        if (wid == 0) {
            if (elect_one()) {
                uint64_t ad = MAKE_SMEM_DESC(smem_base + OFF_A(b));
                uint64_t bd = MAKE_SMEM_DESC(smem_base + OFF_B(b));
#pragma unroll
                for (int s = 0; s < 4; s++)
                    mma_f16_ss(tmem_base, ad + s * 2, bd + s * 2, GEMM_IDESC,
                               (c > 0) || (s > 0));
                TCGEN05_COMMIT(smem_base + OFF_MBAR + b * 8);
            }
        }
        if (c + 1 < NCH) {
            if (c >= 1) {
                // wait for chunk c-1's MMA before overwriting its buffer
                if (b == 1) { mbar_wait(smem_base + OFF_MBAR, ph0); ph0 ^= 1; }
                else        { mbar_wait(smem_base + OFF_MBAR + 8, ph1); ph1 ^= 1; }
            }
            int nb = b ^ 1;
            load_tile(smem, OFF_A(nb), g_Abf + (size_t)k0 * KDIM + (c + 1) * GK);
            load_tile(smem, OFF_B(nb), g_Gbf + (size_t)t0 * KDIM + (c + 1) * GK);
            FENCE_PROXY_ASYNC();
            __syncthreads();
        }
    }
    // drain both queues
    mbar_wait(smem_base + OFF_MBAR, ph0);
    mbar_wait(smem_base + OFF_MBAR + 8, ph1);
    TCGEN05_FENCE_AFTER();

    // ---- epilogue: 8 warps; warp w covers rows (w&3)*32, cols (w>=4)?64:0 ----
    int k = k0 + (wid & 3) * 32 + lid;
    int coloff = (wid >= 4) ? 64 : 0;
    float mu = g_Mu0[k];
    double lsum = 0.0;

#pragma unroll
    for (int half = 0; half < 2; half++) {
        uint32_t dr[32];
        TCGEN05_LD_X32(dr, tmem_base + coloff + half * 32);
        TCGEN05_WAIT_LD();
        int tb = t0 + coloff + half * 32;
        const float* orow = obs + (size_t)k * NDIM + tb;
        float* l1row = out_lam1 + (size_t)k * NDIM + tb;
        float* l0row = out_lams0 + (size_t)k * NDIM + tb;
#pragma unroll
        for (int j = 0; j < 32; j += 4) {
            float4 o = *(const float4*)(orow + j);
            float4 l1;
            l1.x = softplus_f(__uint_as_float(dr[j]));
            l1.y = softplus_f(__uint_as_float(dr[j + 1]));
            l1.z = softplus_f(__uint_as_float(dr[j + 2]));
            l1.w = softplus_f(__uint_as_float(dr[j + 3]));
            if (tb + j == 0) l1.x = 0.0f;   // t == 0 branch
            if (full_out) {
                // scalar stores: bases are 4B-offset, 16B vectors would fault
                l1row[j]     = l1.x;
                l1row[j + 1] = l1.y;
                l1row[j + 2] = l1.z;
                l1row[j + 3] = l1.w;
                l0row[j]     = mu;
                l0row[j + 1] = mu;
                l0row[j + 2] = mu;
                l0row[j + 3] = mu;
            }
            lsum += (double)(o.x * logf(mu + l1.x + 1e-5f) - mu - l1.x);
            lsum += (double)(o.y * logf(mu + l1.y + 1e-5f) - mu - l1.y);
            lsum += (double)(o.z * logf(mu + l1.z + 1e-5f) - mu - l1.z);
            lsum += (double)(o.w * logf(mu + l1.w + 1e-5f) - mu - l1.w);
        }
    }
    TCGEN05_FENCE_BEFORE();

    // block reduce double partials (reuse tile SMEM)
    double* dred = (double*)(smem + OFF_A(0));
    __syncthreads();
    dred[tid] = lsum;
    __syncthreads();
    for (int off = 128; off > 0; off >>= 1) {
        if (tid < off) dred[tid] += dred[tid + off];
        __syncthreads();
    }
    if (tid == 0)
        g_partials[blockIdx.y * gridDim.x + blockIdx.x] = dred[0];

    if (tid == 0) {
        MBARRIER_INVAL(smem_base + OFF_MBAR);
        MBARRIER_INVAL(smem_base + OFF_MBAR + 8);
    }
    __syncthreads();
    if (wid == 0)
        TCGEN05_DEALLOC(tmem_base, 128);

#else  // ---------------- SIMT fallback (non-'a' PTX pass; never runs on bench GPU)
    int tx = tid & 15;             // t sub-tile
    int ty = tid >> 4;             // k sub-tile
    float acc[8][8];
#pragma unroll
    for (int i = 0; i < 8; i++)
#pragma unroll
        for (int j = 0; j < 8; j++) acc[i][j] = 0.0f;

    for (int jj = 0; jj < KDIM; jj++) {
        float a[8], b[8];
#pragma unroll
        for (int i = 0; i < 8; i++)
            a[i] = __bfloat162float(g_Abf[(size_t)(k0 + ty * 8 + i) * KDIM + jj]);
#pragma unroll
        for (int j = 0; j < 8; j++)
            b[j] = __bfloat162float(g_Gbf[(size_t)(t0 + tx * 8 + j) * KDIM + jj]);
#pragma unroll
        for (int i = 0; i < 8; i++)
#pragma unroll
            for (int j = 0; j < 8; j++) acc[i][j] = fmaf(a[i], b[j], acc[i][j]);
    }

    double lsum = 0.0;
#pragma unroll
    for (int i = 0; i < 8; i++) {
        int k = k0 + ty * 8 + i;
        float mu = g_Mu0[k];
#pragma unroll
        for (int j = 0; j < 8; j++) {
            int t = t0 + tx * 8 + j;
            float lam = softplus_f(acc[i][j]);
            if (t == 0) lam = 0.0f;
            size_t idx = (size_t)k * NDIM + t;
            if (full_out) {
                out_lams0[idx] = mu;
                out_lam1[idx]  = lam;
            }
            float o = obs[idx];
            lsum += (double)(o * logf(mu + lam + 1e-5f) - mu - lam);
        }
    }
    double* dred = (double*)smem;
    dred[tid] = lsum;
    __syncthreads();
    for (int off = 128; off > 0; off >>= 1) {
        if (tid < off) dred[tid] += dred[tid + off];
        __syncthreads();
    }
    if (tid == 0)
        g_partials[blockIdx.y * gridDim.x + blockIdx.x] = dred[0];
#endif
}

// ---------------------------------------------------------------------------
// Kernel 5: deterministic final reduction of 1024 double partials -> out[0]
// ---------------------------------------------------------------------------
__global__ void final_reduce_kernel(float* __restrict__ out) {
    __shared__ double dred[256];
    int tid = threadIdx.x;
    double s = 0.0;
    for (int i = tid; i < 1024; i += 256) s += g_partials[i];
    dred[tid] = s;
    __syncthreads();
    for (int off = 128; off > 0; off >>= 1) {
        if (tid < off) dred[tid] += dred[tid + off];
        __syncthreads();
    }
    if (tid == 0) out[0] = (float)dred[0];
}

// ---------------------------------------------------------------------------
extern "C" void kernel_launch(void* const* d_in, const int* in_sizes, int n_in,
                              void* d_out, int out_size) {
    const float* obs   = (const float*)d_in[0];   // [K, N]
    const float* Beta  = (const float*)d_in[1];   // [K]
    const float* Alpha = (const float*)d_in[2];   // [K, K]
    float* out = (float*)d_out;

    cudaFuncSetAttribute(gemm_kernel,
                         cudaFuncAttributeMaxDynamicSharedMemorySize, GEMM_SMEM);

    carry_kernel<<<KDIM, NCHUNK>>>(obs, Beta);
    convA_kernel<<<KDIM, 256>>>(Alpha);
    emit_kernel<<<dim3(NCHUNK, KDIM / 128), 128>>>(obs, Beta);

    dim3 grid(NDIM / GN, KDIM / GM);   // (128, 8)
    gemm_kernel<<<grid, 256, GEMM_SMEM>>>(obs, out, (long long)out_size);

    final_reduce_kernel<<<1, 256>>>(out);
}